// round 5
// baseline (speedup 1.0000x reference)
#include <cuda_runtime.h>

typedef unsigned long long ull;
typedef ulonglong2 ull2;

#define T_LEN 8192
#define NLAG  64

// skew4 layout: phys(i) = i + 4*(i>>4)  (stride 20 per 16-elem chunk).
// Preserves mod-4 alignment -> 16B LDS.128; stride-20 is conflict-free
// for both .64 and .128 shared loads.
#define PHYS_MAX 10320   // phys(8255)=10315, padded
#define SK4(u) ((u) + 4 * ((u) >> 4))

__device__ __forceinline__ ull2 lds128(const float* p) {
    return *reinterpret_cast<const ull2*>(p);
}
__device__ __forceinline__ void fma2(ull& d, ull a, ull b) {
    asm("fma.rn.f32x2 %0, %1, %2, %0;" : "+l"(d) : "l"(a), "l"(b));
}
__device__ __forceinline__ ull pk(float lo, float hi) {
    ull r;
    asm("mov.b64 %0, {%1, %2};" : "=l"(r) : "f"(lo), "f"(hi));
    return r;
}
__device__ __forceinline__ float2 asf2(ull v) {   // unpack: ptxas aliases reg pair
    float2 f;
    asm("mov.b64 {%0, %1}, %2;" : "=f"(f.x), "=f"(f.y) : "l"(v));
    return f;
}
__device__ __forceinline__ float pksum(ull v) {
    float2 f = asf2(v);
    return f.x + f.y;
}

// One lag-group: lags K0..K0+15 (K0 = 1+16g, K0 mod 4 == 1).
// W[i] (i=0..15) = 64-bit pair covering w[2i-1], w[2i]  (w = x[t+K0+...]).
// All shared-memory offsets are compile-time immediates.
template<int K0>
__device__ __forceinline__ void corr_group(const float* __restrict__ sm, int tt,
                                           ull* __restrict__ acc,
                                           float* __restrict__ eacc)
{
#pragma unroll 1
    for (int seg = 0; seg < 8; ++seg) {
        const float* p = sm + seg * 1280 + tt * 20;   // phys(seg*1024 + tt*16)

        ull W[16];
        ull Au[8];
        {   // preload W pairs [0..9] (5x LDS.128) + A pairs [0..1]
            ull2 q0 = lds128(p + SK4(K0 - 1));      W[0] = q0.x; W[1] = q0.y;
            ull2 q1 = lds128(p + SK4(K0 + 3));      W[2] = q1.x; W[3] = q1.y;
            ull2 q2 = lds128(p + SK4(K0 + 7));      W[4] = q2.x; W[5] = q2.y;
            ull2 q3 = lds128(p + SK4(K0 + 11));     W[6] = q3.x; W[7] = q3.y;
            ull2 q4 = lds128(p + SK4(K0 + 15));     W[8] = q4.x; W[9] = q4.y;
            ull2 a0 = lds128(p);                    Au[0] = a0.x; Au[1] = a0.y;
        }

        // m == 0 leading edges: eacc[e] += a0 * w[2e]   (w[2e] = W[e].y)
        const float a0 = asf2(Au[0]).x;
#pragma unroll
        for (int e = 0; e < 8; ++e) eacc[e] += a0 * asf2(W[e]).y;

        float prev = 0.f;   // a[2m-1] carried between steps
#pragma unroll
        for (int m = 0; m < 8; ++m) {
            // slide loads (all offsets compile-time)
            if (m == 1) { ull2 q = lds128(p + 4);             Au[2] = q.x; Au[3] = q.y; }
            if (m == 3) { ull2 q = lds128(p + 8);             Au[4] = q.x; Au[5] = q.y; }
            if (m == 5) { ull2 q = lds128(p + 12);            Au[6] = q.x; Au[7] = q.y; }
            if (m == 2) { ull2 q = lds128(p + SK4(K0 + 19));  W[10] = q.x; W[11] = q.y; }
            if (m == 4) { ull2 q = lds128(p + SK4(K0 + 23));  W[12] = q.x; W[13] = q.y; }
            if (m == 6) { ull2 q = lds128(p + SK4(K0 + 27));  W[14] = q.x; W[15] = q.y; }

            // odd dk = 2e+1: aligned A pair x W pair (both direct LDS.128 results)
#pragma unroll
            for (int e = 0; e < 8; ++e) fma2(acc[2 * e + 1], Au[m], W[m + e + 1]);

            // even dk = 2e: shifted A pair {a[2m-1], a[2m]} x W[m+e]
            const float2 Af = asf2(Au[m]);
            if (m > 0) {
                const ull Ap = pk(prev, Af.x);
#pragma unroll
                for (int e = 0; e < 8; ++e) fma2(acc[2 * e], Ap, W[m + e]);
            }
            prev = Af.y;
        }

        // m == 7 trailing edges: eacc[e] += a15 * w[15+2e]   (= W[e+8].x)
        const float a15 = prev;
#pragma unroll
        for (int e = 0; e < 8; ++e) eacc[e] += a15 * asf2(W[e + 8]).x;
    }
}

__global__ __launch_bounds__(256, 3)
void autocorr_kernel(const float* __restrict__ X, float* __restrict__ out)
{
    __shared__ __align__(16) float sm[PHYS_MAX];
    __shared__ float red[8][16];
    __shared__ float wsum[8], wsq[8];
    __shared__ float stats[2];   // [0]=mean, [1]=1/var0

    const int tid = threadIdx.x;
    const int b   = blockIdx.x;
    const float4* Xr = reinterpret_cast<const float4*>(X + (size_t)b * T_LEN);

    // ---------------- Phase 1: load, mean & sumsq, centered skewed store
    float4 xv[8];
    float s = 0.f, q = 0.f;
#pragma unroll
    for (int r = 0; r < 8; ++r) {
        xv[r] = Xr[tid + r * 256];
        s += xv[r].x + xv[r].y + xv[r].z + xv[r].w;
        q += xv[r].x * xv[r].x + xv[r].y * xv[r].y
           + xv[r].z * xv[r].z + xv[r].w * xv[r].w;
    }
#pragma unroll
    for (int o = 16; o > 0; o >>= 1) {
        s += __shfl_xor_sync(0xffffffffu, s, o);
        q += __shfl_xor_sync(0xffffffffu, q, o);
    }
    if ((tid & 31) == 0) { wsum[tid >> 5] = s; wsq[tid >> 5] = q; }
    __syncthreads();
    if (tid == 0) {
        float S = 0.f, Q = 0.f;
#pragma unroll
        for (int i = 0; i < 8; ++i) { S += wsum[i]; Q += wsq[i]; }
        float mean = S * (1.f / (float)T_LEN);
        stats[0] = mean;
        stats[1] = 1.f / (Q - (float)T_LEN * mean * mean);  // 1/T cancels in ratio
    }
    __syncthreads();
    const float mean = stats[0];

#pragma unroll
    for (int r = 0; r < 8; ++r) {
        int i0 = (tid + r * 256) * 4;        // i0 mod 16 in {0,4,8,12}: same skew
        int pp = i0 + 4 * (i0 >> 4);         // pp mod 4 == 0 -> STS.128
        *reinterpret_cast<float4*>(&sm[pp]) =
            make_float4(xv[r].x - mean, xv[r].y - mean, xv[r].z - mean, xv[r].w - mean);
    }
    if (tid < NLAG) {                        // zero pad -> t<T-k bound handled for free
        int i = T_LEN + tid;
        sm[i + 4 * (i >> 4)] = 0.f;
    }
    __syncthreads();

    // ---------------- Phase 2: lag-group register-tiled correlation
    const int g  = tid >> 6;
    const int tt = tid & 63;

    ull acc[16];
#pragma unroll
    for (int i = 0; i < 16; ++i) acc[i] = 0ull;
    float eacc[8];
#pragma unroll
    for (int i = 0; i < 8; ++i) eacc[i] = 0.f;

    switch (g) {
        case 0: corr_group<1 >(sm, tt, acc, eacc); break;
        case 1: corr_group<17>(sm, tt, acc, eacc); break;
        case 2: corr_group<33>(sm, tt, acc, eacc); break;
        default: corr_group<49>(sm, tt, acc, eacc); break;
    }

    // ---------------- Phase 3: reduce, normalize, store
    float v[16];
#pragma unroll
    for (int i = 0; i < 16; ++i) v[i] = pksum(acc[i]);
#pragma unroll
    for (int e = 0; e < 8; ++e) v[2 * e] += eacc[e];
#pragma unroll
    for (int o = 16; o > 0; o >>= 1) {
#pragma unroll
        for (int i = 0; i < 16; ++i)
            v[i] += __shfl_xor_sync(0xffffffffu, v[i], o);
    }
    if ((tid & 31) == 0) {
        int wid = tid >> 5;
#pragma unroll
        for (int i = 0; i < 16; ++i) red[wid][i] = v[i];
    }
    __syncthreads();
    if (tid < 64) {
        int gg = tid >> 4, dk = tid & 15;    // lag = 16*gg + dk + 1 -> out col = tid
        float sum = red[2 * gg][dk] + red[2 * gg + 1][dk];
        out[(size_t)b * NLAG + tid] = sum * stats[1];
    }
}

extern "C" void kernel_launch(void* const* d_in, const int* in_sizes, int n_in,
                              void* d_out, int out_size)
{
    const float* X = (const float*)d_in[0];
    float* out = (float*)d_out;
    const int B = in_sizes[0] / T_LEN;   // 4096
    autocorr_kernel<<<B, 256>>>(X, out);
}

// round 6
// speedup vs baseline: 1.0343x; 1.0343x over previous
#include <cuda_runtime.h>

typedef unsigned long long ull;

#define T_LEN 8192
#define NLAG  64

// skew2 layout: phys(i) = i + 2*(i>>4)  (stride 18 per 16-elem chunk,
// parity-preserving -> logical-even pairs stay 8B-aligned for LDS.64;
// stride 18 across lanes: bank(9l mod 32) -> conflict-free, gcd(9,32)=1)
#define PHYS_N 9288            // phys(8255)=9285, padded
#define SK(u)  ((u) + 2 * ((u) >> 4))
#define DSMEM_BYTES (2 * PHYS_N * 4)

__device__ __forceinline__ ull lds64(const float* p) {
    return *reinterpret_cast<const ull*>(p);
}
__device__ __forceinline__ void fma2(ull& d, ull a, ull b) {
    asm("fma.rn.f32x2 %0, %1, %2, %0;" : "+l"(d) : "l"(a), "l"(b));
}
__device__ __forceinline__ float pksum(ull v) {   // epilogue only
    float lo, hi;
    asm("mov.b64 {%0, %1}, %2;" : "=f"(lo), "=f"(hi) : "l"(v));
    return lo + hi;
}

// Lag-group K0..K0+15 (K0 = 1+16g, odd). Dual-parity pairing:
//   acc[dk] covers lag k = K0+dk via {x[2m],x[2m+1]} . {x[2m+k],x[2m+1+k]}
//   k odd  (dk=2e):   W2[j]=copy2 pair @ logical 2j+K0-1  (j=m+e)
//   k even (dk=2e+1): W1[j]=copy1 pair @ logical 2j+K0+1  (j=m+e)
// Every operand is a direct aligned LDS.64 — zero packs, zero unpacks.
template<int K0>
__device__ __forceinline__ void corr_group(const float* __restrict__ sm1,
                                           const float* __restrict__ sm2,
                                           int tt, ull* __restrict__ acc)
{
#pragma unroll 1
    for (int seg = 0; seg < 8; ++seg) {
        const float* p1 = sm1 + seg * 1152 + tt * 18;   // phys(seg*1024 + tt*16)
        const float* p2 = sm2 + seg * 1152 + tt * 18;

        ull W1[15], W2[15];
#pragma unroll
        for (int j = 0; j < 9; ++j) {
            W1[j] = lds64(p1 + SK(2 * j + K0 + 1));
            W2[j] = lds64(p2 + SK(2 * j + K0 - 1));
        }

#pragma unroll
        for (int m = 0; m < 8; ++m) {
            const ull A = lds64(p1 + 2 * m);            // 2m < 16 -> no skew term
            if (m < 6) {                                // slide both windows
                W1[m + 9] = lds64(p1 + SK(2 * (m + 9) + K0 + 1));
                W2[m + 9] = lds64(p2 + SK(2 * (m + 9) + K0 - 1));
            }
#pragma unroll
            for (int e = 0; e < 8; ++e) {
                fma2(acc[2 * e],     A, W2[m + e]);     // odd  k = K0+2e
                fma2(acc[2 * e + 1], A, W1[m + e]);     // even k = K0+2e+1
            }
        }
    }
}

__global__ __launch_bounds__(256, 3)
void autocorr_kernel(const float* __restrict__ X, float* __restrict__ out)
{
    extern __shared__ __align__(16) float dsm[];
    float* sm1 = dsm;             // copy1: xc[i]   (skew2)
    float* sm2 = dsm + PHYS_N;    // copy2: xc[i+1] (skew2)

    __shared__ float red[8][16];
    __shared__ float wsum[8], wsq[8];
    __shared__ float stats[2];    // [0]=mean, [1]=1/var0

    const int tid = threadIdx.x;
    const int b   = blockIdx.x;
    const float4* Xr = reinterpret_cast<const float4*>(X + (size_t)b * T_LEN);

    // ---------------- Phase 1: load, mean & sumsq, centered dual stores
    float4 xv[8];
    float s = 0.f, q = 0.f;
#pragma unroll
    for (int r = 0; r < 8; ++r) {
        xv[r] = Xr[tid + r * 256];
        s += xv[r].x + xv[r].y + xv[r].z + xv[r].w;
        q += xv[r].x * xv[r].x + xv[r].y * xv[r].y
           + xv[r].z * xv[r].z + xv[r].w * xv[r].w;
    }
#pragma unroll
    for (int o = 16; o > 0; o >>= 1) {
        s += __shfl_xor_sync(0xffffffffu, s, o);
        q += __shfl_xor_sync(0xffffffffu, q, o);
    }
    if ((tid & 31) == 0) { wsum[tid >> 5] = s; wsq[tid >> 5] = q; }
    __syncthreads();
    if (tid == 0) {
        float S = 0.f, Q = 0.f;
#pragma unroll
        for (int i = 0; i < 8; ++i) { S += wsum[i]; Q += wsq[i]; }
        float mean = S * (1.f / (float)T_LEN);
        stats[0] = mean;
        stats[1] = 1.f / (Q - (float)T_LEN * mean * mean);  // 1/T cancels in ratio
    }
    __syncthreads();
    const float mean = stats[0];

#pragma unroll
    for (int r = 0; r < 8; ++r) {
        const int i0 = (tid + r * 256) * 4;
        const float v0 = xv[r].x - mean, v1 = xv[r].y - mean;
        const float v2 = xv[r].z - mean, v3 = xv[r].w - mean;
        // copy1: aligned pair stores (i0 mod 16 in {0,4,8,12} -> same skew)
        const int p = i0 + 2 * (i0 >> 4);
        *reinterpret_cast<float2*>(&sm1[p])     = make_float2(v0, v1);
        *reinterpret_cast<float2*>(&sm1[p + 2]) = make_float2(v2, v3);
        // copy2: value of logical t goes to slot t-1
        if (i0 > 0) { const int j = i0 - 1; sm2[j + 2 * (j >> 4)] = v0; }
        else        { /* t==0 unused in copy2 */ }
        { const int j = i0;     sm2[j + 2 * (j >> 4)] = v1; }
        { const int j = i0 + 1; sm2[j + 2 * (j >> 4)] = v2; }
        { const int j = i0 + 2; sm2[j + 2 * (j >> 4)] = v3; }
    }
    if (tid < NLAG) {   // zero pads: x[8192..8255] = 0 in both copies
        const int i1 = T_LEN + tid;
        sm1[i1 + 2 * (i1 >> 4)] = 0.f;
        const int i2 = T_LEN - 1 + tid;
        sm2[i2 + 2 * (i2 >> 4)] = 0.f;
    }
    __syncthreads();

    // ---------------- Phase 2: lag-group correlation (pure LDS.64 + FMA2)
    const int g  = tid >> 6;
    const int tt = tid & 63;

    ull acc[16];
#pragma unroll
    for (int i = 0; i < 16; ++i) acc[i] = 0ull;

    switch (g) {
        case 0: corr_group<1 >(sm1, sm2, tt, acc); break;
        case 1: corr_group<17>(sm1, sm2, tt, acc); break;
        case 2: corr_group<33>(sm1, sm2, tt, acc); break;
        default: corr_group<49>(sm1, sm2, tt, acc); break;
    }

    // ---------------- Phase 3: reduce, normalize, store
    float v[16];
#pragma unroll
    for (int i = 0; i < 16; ++i) v[i] = pksum(acc[i]);
#pragma unroll
    for (int o = 16; o > 0; o >>= 1) {
#pragma unroll
        for (int i = 0; i < 16; ++i)
            v[i] += __shfl_xor_sync(0xffffffffu, v[i], o);
    }
    if ((tid & 31) == 0) {
        int wid = tid >> 5;
#pragma unroll
        for (int i = 0; i < 16; ++i) red[wid][i] = v[i];
    }
    __syncthreads();
    if (tid < 64) {
        int gg = tid >> 4, dk = tid & 15;   // lag = 16*gg + dk + 1 -> out col = tid
        float sum = red[2 * gg][dk] + red[2 * gg + 1][dk];
        out[(size_t)b * NLAG + tid] = sum * stats[1];
    }
}

extern "C" void kernel_launch(void* const* d_in, const int* in_sizes, int n_in,
                              void* d_out, int out_size)
{
    const float* X = (const float*)d_in[0];
    float* out = (float*)d_out;
    const int B = in_sizes[0] / T_LEN;   // 4096

    static int attr_done = 0;            // idempotent attribute set (not a guard
    if (!attr_done) {                    // on work — launch always happens)
        cudaFuncSetAttribute(autocorr_kernel,
                             cudaFuncAttributeMaxDynamicSharedMemorySize,
                             DSMEM_BYTES);
        attr_done = 1;
    }
    autocorr_kernel<<<B, 256, DSMEM_BYTES>>>(X, out);
}